// round 7
// baseline (speedup 1.0000x reference)
#include <cuda_runtime.h>
#include <stdint.h>

#define NOPP 3
#define NS   80
#define NA   6
#define DD   512
#define RB   4      // batch rows per block
#define TPB  320    // 4 rows * 80 samples, one sample per thread

// entropy accumulator: fixed-point 2^41, reset by the last block each launch
__device__ unsigned long long g_entacc;
__device__ unsigned int g_ticket;

// ---------------- threefry2x32, key=(0,42), counter=(0,i); out = x0^x1 ----------------
__device__ __forceinline__ uint32_t tf_fold(uint32_t c1)
{
    const uint32_t KS1 = 42u;
    const uint32_t KS2 = 0x1BD11BDAu ^ 42u;   // ks0 = 0
    uint32_t x0 = 0u, x1 = c1 + KS1;
#define TFR(r) { x0 += x1; x1 = __funnelshift_l(x1, x1, (r)); x1 ^= x0; }
    TFR(13) TFR(15) TFR(26) TFR(6)
    x0 += KS1; x1 += KS2 + 1u;
    TFR(17) TFR(29) TFR(16) TFR(24)
    x0 += KS2; x1 += 2u;
    TFR(13) TFR(15) TFR(26) TFR(6)
    x1 += KS1 + 3u;
    TFR(17) TFR(29) TFR(16) TFR(24)
    x0 += KS1; x1 += KS2 + 4u;
    TFR(13) TFR(15) TFR(26) TFR(6)
    x0 += KS2; x1 += 5u;
#undef TFR
    return x0 ^ x1;
}

__global__ void __launch_bounds__(TPB, 3) kfused(
    const float* __restrict__ x, const float* __restrict__ Wopp,
    const float* __restrict__ bopp, const float* __restrict__ W,
    const float* __restrict__ bias, float* __restrict__ out,
    int B, int out_size)
{
    // pool: GEMM x-staging (RB*DD = 2048 floats), later reused as the
    // 7*TPB = 2240-float reduction buffer. 2560 floats = 10 KB.
    __shared__ float pool[2560];
    __shared__ float vals[RB][25];
    __shared__ float einv_s[RB][20];
    __shared__ float dist_s[RB][20];
    __shared__ float base_s[RB][8];
    __shared__ float W2s[18 * 8];
    __shared__ float entkb[RB * 3];

    int tid  = threadIdx.x;
    int warp = tid >> 5;
    int lane = tid & 31;
    int b0   = blockIdx.x * RB;

    if (tid < 18 * NA) W2s[(tid / 6) * 8 + (tid % 6)] = W[DD * NA + tid];

    // ---- stage x rows into pool ----
    if (b0 + RB <= B) {
        const float4* x4 = reinterpret_cast<const float4*>(x + (size_t)b0 * DD);
        float4* xs4 = reinterpret_cast<float4*>(pool);
        for (int i = tid; i < RB * DD / 4; i += TPB) xs4[i] = x4[i];
    } else {
        for (int i = tid; i < RB * DD; i += TPB) {
            int r = i / DD;
            pool[i] = (b0 + r < B) ? x[(size_t)(b0 + r) * DD + (i % DD)] : 0.0f;
        }
    }

    // ---- GEMM: warps 0..7 each own 3 output columns ----
    if (warp < 8) {
        float w0[16], w1[16], w2[16];
        int c = 3 * warp;
        const float* s0 = (c + 0 < 18) ? (Wopp + (size_t)((c + 0) / 6) * DD * NA + ((c + 0) % 6))
                                       : (W + (c + 0 - 18));
        const float* s1 = (c + 1 < 18) ? (Wopp + (size_t)((c + 1) / 6) * DD * NA + ((c + 1) % 6))
                                       : (W + (c + 1 - 18));
        const float* s2 = (c + 2 < 18) ? (Wopp + (size_t)((c + 2) / 6) * DD * NA + ((c + 2) % 6))
                                       : (W + (c + 2 - 18));
#pragma unroll
        for (int j = 0; j < 16; j++) {
            size_t idx = (size_t)(lane + 32 * j) * NA;
            w0[j] = s0[idx]; w1[j] = s1[idx]; w2[j] = s2[idx];
        }
        __syncthreads();   // xs staged
#pragma unroll
        for (int r = 0; r < RB; r++) {
            const float* xr = pool + r * DD + lane;
            float a0 = 0.f, a1 = 0.f, a2 = 0.f;
#pragma unroll
            for (int j = 0; j < 16; j++) {
                float xv = xr[32 * j];
                a0 = fmaf(xv, w0[j], a0);
                a1 = fmaf(xv, w1[j], a1);
                a2 = fmaf(xv, w2[j], a2);
            }
#pragma unroll
            for (int off = 16; off; off >>= 1) {
                a0 += __shfl_down_sync(0xffffffffu, a0, off);
                a1 += __shfl_down_sync(0xffffffffu, a1, off);
                a2 += __shfl_down_sync(0xffffffffu, a2, off);
            }
            if (lane == 0) {
                vals[r][c + 0] = a0;
                vals[r][c + 1] = a1;
                vals[r][c + 2] = a2;
            }
        }
    } else {
        __syncthreads();   // matching barrier for warps 8-9
    }
    __syncthreads();

    // ---- postprocess: softmax/einv/dist/entropy + agent base logits ----
    if (tid < RB * 3) {
        int r = tid / 3, k = tid % 3, b = b0 + r;
        if (b < B) {
            float l[NA], m = -1e30f;
#pragma unroll
            for (int a = 0; a < NA; a++) {
                l[a] = vals[r][k * 6 + a] + bopp[k * 6 + a];
                m = fmaxf(m, l[a]);
            }
            float e[NA], S = 0.0f;
#pragma unroll
            for (int a = 0; a < NA; a++) { e[a] = expf(l[a] - m); S += e[a]; }
            float logS = logf(S);
            float ent = 0.0f;
            size_t distoff = (size_t)B * NA + ((size_t)k * B + b) * NA;
#pragma unroll
            for (int a = 0; a < NA; a++) {
                float d = e[a] / S;
                dist_s[r][k * 6 + a] = d;
                einv_s[r][k * 6 + a] = expf(-l[a]);
                ent -= d * ((l[a] - m) - logS);
                if (out_size >= B * 24) out[distoff + a] = d;
            }
            entkb[tid] = ent;
        } else entkb[tid] = 0.0f;
    } else if (tid < RB * 3 + RB * 6) {
        int t2 = tid - RB * 3;
        int r = t2 / 6, a = t2 % 6, b = b0 + r;
        if (b < B) base_s[r][a] = vals[r][18 + a] + bias[a];
    }
    __syncthreads();

    // ---- entropy: fixed-point atomic + last-block ticket (deterministic) ----
    if (tid == 0) {
        float part = 0.0f;
        for (int i = 0; i < RB * 3; i++) part += entkb[i];
        unsigned long long q =
            (unsigned long long)__double2ll_rn((double)part * 2199023255552.0); // 2^41
        atomicAdd(&g_entacc, q);
        __threadfence();
        unsigned int old = atomicAdd(&g_ticket, 1u);
        if (old == gridDim.x - 1) {
            unsigned long long tot = atomicExch(&g_entacc, 0ull);
            atomicExch(&g_ticket, 0u);
            if (out_size >= B * 24 + 1)
                out[(size_t)B * 24] =
                    (float)((double)tot * (1.0 / 2199023255552.0) / (3.0 * (double)B));
        }
    }

    // ---- sampling: one (row, sample) per thread ----
    int r = tid / 80;
    int s = tid - r * 80;
    int b = b0 + r;

    float num[NA] = {0, 0, 0, 0, 0, 0}, den = 0.0f;
    if (b < B) {
        float p1 = 1.0f, l[NA];
#pragma unroll
        for (int a = 0; a < NA; a++) l[a] = base_s[r][a];
#pragma unroll
        for (int k = 0; k < 3; k++) {
            uint32_t c0 = (uint32_t)(((k * NS + s) * B + b) * NA);
            uint32_t mp = 0xFFFFFFFFu;
#pragma unroll
            for (int a = 0; a < NA; a++) {      // 6 independent hash chains -> ILP
                uint32_t bits = tf_fold(c0 + (uint32_t)a);
                // u = f - 1 in [0,1); v = log2(u) * einv  (all v < 0).
                // argmax v == argmin t*einv. For negatives, float order is the
                // REVERSE of uint order, so umin(bits) selects max v; ties pick
                // the lowest action (matches jax argmax-first-index).
                float f = __uint_as_float((bits >> 9) | 0x3f800000u) - 1.0f;
                float v = __log2f(f) * einv_s[r][k * 6 + a];
                uint32_t pv = (__float_as_uint(v) & 0xFFFFFFF8u) | (uint32_t)a;
                mp = (mp < pv) ? mp : pv;
            }
            int amin = (int)(mp & 7u);
            p1 *= dist_s[r][k * 6 + amin];
#pragma unroll
            for (int a = 0; a < NA; a++) l[a] += W2s[(k * 6 + amin) * 8 + a];
        }
        float m = l[0];
#pragma unroll
        for (int a = 1; a < NA; a++) m = fmaxf(m, l[a]);
        float e[NA], S = 0.0f;
#pragma unroll
        for (int a = 0; a < NA; a++) { e[a] = __expf(l[a] - m); S += e[a]; }
        float w = p1 / S;
#pragma unroll
        for (int a = 0; a < NA; a++) num[a] = w * e[a];
        den = p1;
    }

    // ---- deterministic combine: pool reused as 7 x TPB reduction buffer ----
    __syncthreads();   // pool (xs) reads done
#pragma unroll
    for (int a = 0; a < NA; a++) pool[a * TPB + tid] = num[a];
    pool[6 * TPB + tid] = den;
    __syncthreads();

    if (tid < RB * 32) {
        int rr = tid >> 5, ll = tid & 31;
        int bb = b0 + rr;
        float part[7];
#pragma unroll
        for (int j = 0; j < 7; j++) {
            int base = j * TPB + rr * 80;
            float p = pool[base + ll] + pool[base + ll + 32];
            if (ll < 16) p += pool[base + ll + 64];
            part[j] = p;
        }
#pragma unroll
        for (int off = 16; off; off >>= 1)
#pragma unroll
            for (int j = 0; j < 7; j++)
                part[j] += __shfl_down_sync(0xffffffffu, part[j], off);
        if (ll == 0 && bb < B) {
            float inv = 1.0f / part[6];
#pragma unroll
            for (int a = 0; a < NA; a++) out[(size_t)bb * NA + a] = part[a] * inv;
        }
    }
}

// ---------------- launch ----------------
extern "C" void kernel_launch(void* const* d_in, const int* in_sizes, int n_in,
                              void* d_out, int out_size)
{
    const float* x    = (const float*)d_in[0];
    const float* Wopp = (const float*)d_in[1];
    const float* bopp = (const float*)d_in[2];
    const float* W    = (const float*)d_in[3];
    const float* bias = (const float*)d_in[4];
    float* out = (float*)d_out;

    int D = in_sizes[1] / (NOPP * NA);   // 512
    int B = in_sizes[0] / D;             // 4096

    int grid = (B + RB - 1) / RB;        // 1024
    kfused<<<grid, TPB>>>(x, Wopp, bopp, W, bias, out, B, out_size);
}